// round 8
// baseline (speedup 1.0000x reference)
#include <cuda_runtime.h>
#include <cuda_fp16.h>
#include <cstdint>

#define DIN       128
#define TILE_B    64
#define NTHREADS  256
#define AST       136     // half stride of staged weight half-tile rows
#define HKST      264     // half stride for Hk/Rk (256 cols + 8 pad)
#define NHT       40      // 20 tiles x 2 half-tiles (64 out-cols each)
#define TEMP_INV  0.17677669529663687f
#define LN_EPS    1e-5f

// smem: sW 2x(64*136h)=34816B, sHk 64*264h=33792B, sRk 33792B,
//       sHX 2048B, sRX 2048B, sP 2048B  => 108544B  (2 CTAs/SM)
#define SMEM_BYTES 108544

__device__ __half g_Wx[1280 * DIN];
__device__ __half g_Wy[1280 * DIN];

__global__ void prep_kernel(const float* __restrict__ w_h, const float* __restrict__ w_r,
                            const float* __restrict__ k_h, const float* __restrict__ k_r) {
    int row = blockIdx.x;
    const float* w; const float* kk; __half* dst;
    if (row < 1280) { w = w_h; kk = k_h; dst = g_Wx + (size_t)row * DIN; }
    else { row -= 1280; w = w_r; kk = k_r; dst = g_Wy + (size_t)row * DIN; }
    int k = threadIdx.x;
    float v;
    if (row < 1024) v = w[(size_t)row * DIN + k];
    else {
        int h = (row - 1024) >> 5, i = (row - 1024) & 31;
        const float* wr = w + (size_t)h * DIN * DIN;
        const float* kr = kk + (size_t)i * DIN;
        float acc = 0.f;
#pragma unroll 8
        for (int j = 0; j < DIN; j++) acc = fmaf(kr[j], wr[(size_t)j * DIN + k], acc);
        v = acc;
    }
    dst[k] = __float2half_rn(v);
}

// ---------------- helpers ----------------
__device__ __forceinline__ uint32_t smem_u32(const void* p) {
    return (uint32_t)__cvta_generic_to_shared(p);
}
__device__ __forceinline__ void ldsm4(uint32_t r[4], uint32_t addr) {
    asm volatile("ldmatrix.sync.aligned.m8n8.x4.shared.b16 {%0,%1,%2,%3}, [%4];"
                 : "=r"(r[0]), "=r"(r[1]), "=r"(r[2]), "=r"(r[3]) : "r"(addr));
}
__device__ __forceinline__ void mma16816(float c[4], const uint32_t a[4], uint32_t b0, uint32_t b1) {
    asm volatile(
        "mma.sync.aligned.m16n8k16.row.col.f32.f16.f16.f32 "
        "{%0,%1,%2,%3}, {%4,%5,%6,%7}, {%8,%9}, {%0,%1,%2,%3};"
        : "+f"(c[0]), "+f"(c[1]), "+f"(c[2]), "+f"(c[3])
        : "r"(a[0]), "r"(a[1]), "r"(a[2]), "r"(a[3]), "r"(b0), "r"(b1));
}
#define CP_COMMIT() asm volatile("cp.async.commit_group;" ::: "memory")

// stage one 64-row x 128-K half-tile of weights
__device__ __forceinline__ void stage(const __half* __restrict__ src, __half* dst, int tid) {
    uint32_t d = smem_u32(dst);
#pragma unroll
    for (int k = 0; k < 4; k++) {
        int i = tid + k * NTHREADS;
        int n = i >> 4, c = (i & 15) * 8;
        asm volatile("cp.async.cg.shared.global [%0], [%1], 16;" ::
                     "r"(d + (uint32_t)(n * AST + c) * 2), "l"(src + n * DIN + c));
    }
}
// half-tile ht source: tile = ht>>1 (0..19), half = ht&1 (out-col block)
__device__ __forceinline__ const __half* ht_src(int ht) {
    int tile = ht >> 1;
    const __half* base;
    if (tile < 4) base = ((tile >> 1) ? g_Wy : g_Wx) + (size_t)(1024 + (tile & 1) * DIN) * DIN;
    else {
        int h = tile - 4;
        base = (h < 8) ? g_Wx + (size_t)h * DIN * DIN : g_Wy + (size_t)(h - 8) * DIN * DIN;
    }
    return base + (size_t)(ht & 1) * 64 * DIN;
}

// build A fragments (16 rows x 128 K) directly from global fp32
__device__ __forceinline__ void build_af(const float* __restrict__ src, int lane, uint32_t af[8][4]) {
    int g = lane >> 2, t = lane & 3;
    const float* r0 = src + (size_t)g * DIN;
    const float* r1 = r0 + 8 * DIN;
#pragma unroll
    for (int ks = 0; ks < 8; ks++) {
        float2 v0 = *(const float2*)(r0 + ks * 16 + 2 * t);
        float2 v1 = *(const float2*)(r1 + ks * 16 + 2 * t);
        float2 v2 = *(const float2*)(r0 + ks * 16 + 8 + 2 * t);
        float2 v3 = *(const float2*)(r1 + ks * 16 + 8 + 2 * t);
        __half2 h0 = __floats2half2_rn(v0.x, v0.y);
        __half2 h1 = __floats2half2_rn(v1.x, v1.y);
        __half2 h2 = __floats2half2_rn(v2.x, v2.y);
        __half2 h3 = __floats2half2_rn(v3.x, v3.y);
        af[ks][0] = *(uint32_t*)&h0; af[ks][1] = *(uint32_t*)&h1;
        af[ks][2] = *(uint32_t*)&h2; af[ks][3] = *(uint32_t*)&h3;
    }
}

// 16m x 32n x 128k warp gemm on a 64x128 half-tile buffer
__device__ __forceinline__ void gemm_w(const uint32_t af[8][4], const __half* sW,
                                       int ncol0, int lane, float acc[4][4]) {
    int brow = (lane & 7) + ((lane >> 4) & 1) * 8;
    int bcoff = ((lane >> 3) & 1) * 8;
    uint32_t b0 = smem_u32(sW + (ncol0 + brow) * AST + bcoff);
    uint32_t b1 = smem_u32(sW + (ncol0 + 16 + brow) * AST + bcoff);
#pragma unroll
    for (int ks = 0; ks < 8; ks++) {
        uint32_t bb0[4], bb1[4];
        ldsm4(bb0, b0 + ks * 32);
        ldsm4(bb1, b1 + ks * 32);
        mma16816(acc[0], af[ks], bb0[0], bb0[1]);
        mma16816(acc[1], af[ks], bb0[2], bb0[3]);
        mma16816(acc[2], af[ks], bb1[0], bb1[1]);
        mma16816(acc[3], af[ks], bb1[2], bb1[3]);
    }
}

__global__ __launch_bounds__(NTHREADS, 2)
void xattn_main(const float* __restrict__ h_emb, const float* __restrict__ r_emb,
                const float* __restrict__ gamma, const float* __restrict__ beta,
                float* __restrict__ out) {
    extern __shared__ char smem_raw[];
    __half* sW = (__half*)smem_raw;                 // 2 x 64*136
    __half* sHk = sW + 2 * 64 * AST;                // 64*264
    __half* sRk = sHk + TILE_B * HKST;              // 64*264
    float* sHX = (float*)(sRk + TILE_B * HKST);     // 64*8
    float* sRX = sHX + TILE_B * 8;                  // 64*8
    float* sP = sRX + TILE_B * 8;                   // 8*64
    float* sT = (float*)sHk;                        // f32 alias, stride 132

    int tid = threadIdx.x;
    int warp = tid >> 5, lane = tid & 31;
    int mi = warp >> 1, ni = warp & 1;              // 4 x 2 warp grid, tile 16x32
    int g = lane >> 2, t = lane & 3;
    int row0 = blockIdx.x * TILE_B;

    // prologue: stage half-tile 0
    stage(ht_src(0), sW, tid); CP_COMMIT();

    // initial A fragments from X
    uint32_t af[8][4];
    build_af(h_emb + (size_t)(row0 + mi * 16) * DIN, lane, af);
    int cur_side = 0;

    float outacc[2][4][4];
#pragma unroll
    for (int oh = 0; oh < 2; oh++)
#pragma unroll
        for (int j = 0; j < 4; j++)
#pragma unroll
            for (int q = 0; q < 4; q++) outacc[oh][j][q] = 0.f;

#pragma unroll 1
    for (int ht = 0; ht < NHT; ht++) {
        __syncthreads();                            // (A) readers of ht-1 done; epilogue STS visible

        if (ht + 1 < NHT) {
            stage(ht_src(ht + 1), sW + ((ht + 1) & 1) * 64 * AST, tid);
            CP_COMMIT();
        }
        if (ht + 1 < NHT) asm volatile("cp.async.wait_group 1;" ::: "memory");
        else              asm volatile("cp.async.wait_group 0;" ::: "memory");
        __syncthreads();                            // (B) half-tile ht visible to all

        // -------- attention once, before first phase-2 half-tile --------
        if (ht == 8) {
            int h0 = lane >> 3, j0 = lane & 7;
#pragma unroll 1
            for (int rr = 0; rr < 8; rr++) {
                int r = warp * 8 + rr;
                const __half2* hp0 = (const __half2*)(sHk + r * HKST + h0 * 32);
                const __half2* hp1 = (const __half2*)(sHk + r * HKST + (h0 + 4) * 32);
                const __half2* rp = (const __half2*)(sRk + r * HKST + j0 * 32);
                float l0 = 0.f, l1 = 0.f;
#pragma unroll
                for (int k2 = 0; k2 < 16; k2++) {
                    float2 bb = __half22float2(rp[k2]);
                    float2 aa = __half22float2(hp0[k2]);
                    float2 cc = __half22float2(hp1[k2]);
                    l0 = fmaf(aa.x, bb.x, fmaf(aa.y, bb.y, l0));
                    l1 = fmaf(cc.x, bb.x, fmaf(cc.y, bb.y, l1));
                }
                float m = fmaxf(l0, l1);
#pragma unroll
                for (int o = 16; o; o >>= 1) m = fmaxf(m, __shfl_xor_sync(0xffffffffu, m, o));
                float e0 = __expf(l0 - m), e1 = __expf(l1 - m);
                float s = e0 + e1;
#pragma unroll
                for (int o = 16; o; o >>= 1) s += __shfl_xor_sync(0xffffffffu, s, o);
                float inv = 1.0f / s;
                e0 *= inv; e1 *= inv;
                sP[warp * 64 + lane] = e0;
                sP[warp * 64 + 32 + lane] = e1;
                __syncwarp();
                if (lane < 8) {
                    float hx = 0.f;
#pragma unroll
                    for (int j = 0; j < 8; j++) hx += sP[warp * 64 + lane * 8 + j];
                    sHX[r * 8 + lane] = hx;
                } else if (lane < 16) {
                    int j = lane - 8;
                    float rx = 0.f;
#pragma unroll
                    for (int h = 0; h < 8; h++) rx += sP[warp * 64 + h * 8 + j];
                    sRX[r * 8 + j] = rx;
                }
                __syncwarp();
            }
            __syncthreads();
        }

        // A-side switch: X(0..3) Y(4..7) X(8..23) Y(24..39)
        int side = (ht < 8) ? (ht >> 2) : ((ht - 8) >> 4);
        if (side != cur_side) {
            const float* src = (side ? r_emb : h_emb) + (size_t)(row0 + mi * 16) * DIN;
            build_af(src, lane, af);
            cur_side = side;
        }

        const __half* sWc = sW + (ht & 1) * 64 * AST;
        float acc[4][4];
#pragma unroll
        for (int j = 0; j < 4; j++)
#pragma unroll
            for (int q = 0; q < 4; q++) acc[j][q] = 0.f;
        gemm_w(af, sWc, ni * 32, lane, acc);

        if (ht < 8) {
            __half* dst = (ht < 4) ? sHk : sRk;
            float sc = (ht < 4) ? TEMP_INV : 1.0f;
            int cb = ((ht >> 1) & 1) * 128 + (ht & 1) * 64 + ni * 32;
            int r = mi * 16 + g;
#pragma unroll
            for (int j = 0; j < 4; j++) {
                int col = cb + j * 8 + 2 * t;
                *(__half2*)(dst + r * HKST + col) =
                    __floats2half2_rn(acc[j][0] * sc, acc[j][1] * sc);
                *(__half2*)(dst + (r + 8) * HKST + col) =
                    __floats2half2_rn(acc[j][2] * sc, acc[j][3] * sc);
            }
        } else {
            int hh = (ht - 8) >> 1;
            int h = hh & 7;
            int oh = ht & 1;
            const float* sS = (hh >> 3) ? sRX : sHX;
            int r = mi * 16 + g;
            float w0 = sS[r * 8 + h];
            float w1 = sS[(r + 8) * 8 + h];
#pragma unroll
            for (int j = 0; j < 4; j++) {
                outacc[oh][j][0] = fmaf(w0, acc[j][0], outacc[oh][j][0]);
                outacc[oh][j][1] = fmaf(w0, acc[j][1], outacc[oh][j][1]);
                outacc[oh][j][2] = fmaf(w1, acc[j][2], outacc[oh][j][2]);
                outacc[oh][j][3] = fmaf(w1, acc[j][3], outacc[oh][j][3]);
            }
        }
    }
    __syncthreads();

    // -------- residual add into f32 scratch (stride 132) --------
    {
        int r = mi * 16 + g;
#pragma unroll
        for (int oh = 0; oh < 2; oh++) {
#pragma unroll
            for (int j = 0; j < 4; j++) {
                int c = oh * 64 + ni * 32 + j * 8 + 2 * t;
                sT[r * 132 + c]     = outacc[oh][j][0] + h_emb[(size_t)(row0 + r) * DIN + c];
                sT[r * 132 + c + 1] = outacc[oh][j][1] + h_emb[(size_t)(row0 + r) * DIN + c + 1];
                sT[(r + 8) * 132 + c]     = outacc[oh][j][2] + h_emb[(size_t)(row0 + r + 8) * DIN + c];
                sT[(r + 8) * 132 + c + 1] = outacc[oh][j][3] + h_emb[(size_t)(row0 + r + 8) * DIN + c + 1];
            }
        }
    }
    __syncthreads();

    // -------- LayerNorm: each warp 8 rows --------
#pragma unroll 1
    for (int rr = 0; rr < 8; rr++) {
        int r = warp * 8 + rr;
        float v[4];
#pragma unroll
        for (int q = 0; q < 4; q++) v[q] = sT[r * 132 + lane + q * 32];
        float sum = v[0] + v[1] + v[2] + v[3];
#pragma unroll
        for (int o = 16; o; o >>= 1) sum += __shfl_xor_sync(0xffffffffu, sum, o);
        float mean = sum * (1.0f / 128.0f);
        float sq = 0.f;
#pragma unroll
        for (int q = 0; q < 4; q++) { v[q] -= mean; sq = fmaf(v[q], v[q], sq); }
#pragma unroll
        for (int o = 16; o; o >>= 1) sq += __shfl_xor_sync(0xffffffffu, sq, o);
        float rstd = rsqrtf(sq * (1.0f / 128.0f) + LN_EPS);
#pragma unroll
        for (int q = 0; q < 4; q++) {
            int cc = lane + q * 32;
            out[(size_t)(row0 + r) * DIN + cc] = fmaf(gamma[cc], v[q] * rstd, beta[cc]);
        }
    }
}

extern "C" void kernel_launch(void* const* d_in, const int* in_sizes, int n_in,
                              void* d_out, int out_size) {
    const float* h_emb = (const float*)d_in[0];
    const float* r_emb = (const float*)d_in[1];
    const float* w_h = (const float*)d_in[2];
    const float* w_r = (const float*)d_in[3];
    const float* k_h = (const float*)d_in[4];
    const float* k_r = (const float*)d_in[5];
    const float* gamma = (const float*)d_in[6];
    const float* beta = (const float*)d_in[7];
    // d_in[8] = mode, always 0 ('normal').

    int Brows = in_sizes[0] / DIN;
    int grid = Brows / TILE_B;

    prep_kernel<<<2560, 128>>>(w_h, w_r, k_h, k_r);

    cudaFuncSetAttribute(xattn_main, cudaFuncAttributeMaxDynamicSharedMemorySize, SMEM_BYTES);
    xattn_main<<<grid, NTHREADS, SMEM_BYTES>>>(h_emb, r_emb, gamma, beta, (float*)d_out);
}